// round 8
// baseline (speedup 1.0000x reference)
#include <cuda_runtime.h>
#include <math.h>

#define BB 512
#define NN 120
#define DD 64
#define ROWS (BB*NN)           // 61440
#define NBINS 32

typedef unsigned long long u64;

// ---------------- scratch (static device arrays; no cudaMalloc) ----------------
__device__ float  g_q[ROWS*DD];
__device__ float  g_k[ROWS*DD];
__device__ float  g_v[ROWS*DD];
__device__ float  g_gam[ROWS];
__device__ float  g_o[ROWS*DD];
// packed twiddles: twp[d2*32+f] = (cos(w*f*2d2), cos(w*f*(2d2+1)), sin(...), sin(...))
__device__ float4 g_twp[1024];
// W repacked over e-pairs: P[e2*32+lane] = (W[2e2][2l], W[2e2+1][2l], W[2e2][2l+1], W[2e2+1][2l+1])
__device__ float4 g_Wqp[1024], g_Wkp[1024], g_Wvp[1024], g_Wop[1024];

// ---------------- f32x2 helpers ----------------
__device__ __forceinline__ u64 fma2(u64 a, u64 b, u64 c) {
    u64 d; asm("fma.rn.f32x2 %0,%1,%2,%3;" : "=l"(d) : "l"(a), "l"(b), "l"(c)); return d;
}
__device__ __forceinline__ u64 mul2(u64 a, u64 b) {
    u64 d; asm("mul.rn.f32x2 %0,%1,%2;" : "=l"(d) : "l"(a), "l"(b)); return d;
}
__device__ __forceinline__ u64 dup2(float v) {
    u64 r; asm("mov.b64 %0,{%1,%1};" : "=l"(r) : "f"(v)); return r;
}
__device__ __forceinline__ float2 unp(u64 v) {
    float a, b; asm("mov.b64 {%0,%1},%2;" : "=f"(a), "=f"(b) : "l"(v));
    return make_float2(a, b);
}
// S' = clip(g*S + delta*k, +-10)
__device__ __forceinline__ u64 upd2(u64 S, u64 k, u64 g, u64 delta) {
    u64 r;
    asm("{\n\t"
        ".reg .f32 lo,hi;\n\t"
        ".reg .b64 t;\n\t"
        "mul.rn.f32x2 t, %2, %3;\n\t"
        "fma.rn.f32x2 t, %4, %1, t;\n\t"
        "mov.b64 {lo,hi}, t;\n\t"
        "min.f32 lo, lo, 0f41200000;\n\t"
        "max.f32 lo, lo, 0fC1200000;\n\t"
        "min.f32 hi, hi, 0f41200000;\n\t"
        "max.f32 hi, hi, 0fC1200000;\n\t"
        "mov.b64 %0, {lo,hi};\n\t"
        "}"
        : "=l"(r) : "l"(S), "l"(k), "l"(delta), "l"(g));
    return r;
}

// ---------------- init: packed twiddles + W e-pair repack ----------------
__global__ void init_kernel(const float* __restrict__ Wq, const float* __restrict__ Wk,
                            const float* __restrict__ Wv, const float* __restrict__ Wo) {
    int i = blockIdx.x * blockDim.x + threadIdx.x;
    if (i < 1024) {
        int d2 = i >> 5, f = i & 31;
        int m0 = (f * (2*d2))     & 63;       // exact modular angle reduction
        int m1 = (f * (2*d2 + 1)) & 63;
        const double w = 2.0 * 3.14159265358979323846 / 64.0;
        g_twp[i] = make_float4((float)cos(w*m0), (float)cos(w*m1),
                               (float)sin(w*m0), (float)sin(w*m1));
    } else if (i < 5120) {
        int s = (i - 1024) >> 10, j = (i - 1024) & 1023;
        int e2 = j >> 5, l = j & 31;
        const float* W = (s == 0) ? Wq : (s == 1) ? Wk : (s == 2) ? Wv : Wo;
        float4*      P = (s == 0) ? g_Wqp : (s == 1) ? g_Wkp : (s == 2) ? g_Wvp : g_Wop;
        int a = (2*e2)*DD + 2*l;
        P[j] = make_float4(W[a], W[a+DD], W[a+1], W[a+DD+1]);
    }
}

// 4-row matvec pass over one packed matrix (even/odd e-partial accumulators)
#define MATVEC_PASS4(Wp, aE, aO)                                            \
    {                                                                       \
        _Pragma("unroll")                                                   \
        for (int r = 0; r < 4; r++) { aE[r] = 0ull; aO[r] = 0ull; }         \
        _Pragma("unroll 4")                                                 \
        for (int e4 = 0; e4 < 16; e4++) {                                   \
            ulonglong2 w0 = Wp[(2*e4)*32 + lane];                           \
            ulonglong2 w1 = Wp[(2*e4+1)*32 + lane];                         \
            _Pragma("unroll")                                               \
            for (int r = 0; r < 4; r++) {                                   \
                ulonglong2 hh = ((const ulonglong2*)sh[warp][r])[e4];       \
                aE[r] = fma2(hh.x, w0.x, aE[r]);                            \
                aO[r] = fma2(hh.x, w0.y, aO[r]);                            \
                aE[r] = fma2(hh.y, w1.x, aE[r]);                            \
                aO[r] = fma2(hh.y, w1.y, aO[r]);                            \
            }                                                               \
        }                                                                   \
    }

// ---------------- fused per-batch kernel: pre -> scan -> post ----------------
__global__ void __launch_bounds__(256, 4) fused_kernel(
    const float* __restrict__ x,  const float* __restrict__ g_norm,
    const float* __restrict__ bv,
    const float* __restrict__ W1, const float* __restrict__ b1,
    const float* __restrict__ W2, const float* __restrict__ b2,
    const float* __restrict__ g_post, const float* __restrict__ bo,
    float* __restrict__ out)
{
    const int b    = blockIdx.x;
    const int warp = threadIdx.x >> 5;
    const int lane = threadIdx.x & 31;
    __shared__ __align__(16) float sh[8][4][DD];
    __shared__ float smag[8][4][NBINS];

    // ================= PRE phase: 4 rows per warp per iteration =================
    {
        float2 gv = ((const float2*)g_norm)[lane];
        float2 bvv = ((const float2*)bv)[lane];
        for (int rb = warp*4; rb < NN; rb += 32) {
            const int row0 = b*NN + rb;

            // ---- zc_rms for 4 rows ----
            #pragma unroll
            for (int r = 0; r < 4; r++) {
                float2 xv = ((const float2*)(x + (row0 + r)*DD))[lane];
                float s = xv.x + xv.y;
                #pragma unroll
                for (int o = 16; o; o >>= 1) s += __shfl_xor_sync(0xffffffffu, s, o);
                float mean = s * (1.0f/64.0f);
                float a0 = xv.x - mean, a1 = xv.y - mean;
                float ss = a0*a0 + a1*a1;
                #pragma unroll
                for (int o = 16; o; o >>= 1) ss += __shfl_xor_sync(0xffffffffu, ss, o);
                float rn = rsqrtf(ss * (1.0f/64.0f) + 1e-8f);
                sh[warp][r][2*lane]   = a0 * rn * gv.x;
                sh[warp][r][2*lane+1] = a1 * rn * gv.y;
            }
            __syncwarp();

            u64 aE[4], aO[4];

            // ---- Q pass ----
            MATVEC_PASS4(((const ulonglong2*)g_Wqp), aE, aO)
            #pragma unroll
            for (int r = 0; r < 4; r++) {
                float2 e0 = unp(aE[r]), e1 = unp(aO[r]);
                float q0 = e0.x + e0.y, q1 = e1.x + e1.y;
                float qs = q0*q0 + q1*q1;
                #pragma unroll
                for (int o = 16; o; o >>= 1) qs += __shfl_xor_sync(0xffffffffu, qs, o);
                float qr = rsqrtf(qs + 1e-8f);
                ((float2*)(g_q + (row0 + r)*DD))[lane] = make_float2(q0*qr, q1*qr);
            }

            // ---- K pass ----
            MATVEC_PASS4(((const ulonglong2*)g_Wkp), aE, aO)
            #pragma unroll
            for (int r = 0; r < 4; r++) {
                float2 e0 = unp(aE[r]), e1 = unp(aO[r]);
                float k0 = e0.x + e0.y, k1 = e1.x + e1.y;
                float ks = k0*k0 + k1*k1;
                #pragma unroll
                for (int o = 16; o; o >>= 1) ks += __shfl_xor_sync(0xffffffffu, ks, o);
                float kr = rsqrtf(ks + 1e-8f);
                ((float2*)(g_k + (row0 + r)*DD))[lane] = make_float2(k0*kr, k1*kr);
            }

            // ---- V pass ----
            MATVEC_PASS4(((const ulonglong2*)g_Wvp), aE, aO)
            #pragma unroll
            for (int r = 0; r < 4; r++) {
                float2 e0 = unp(aE[r]), e1 = unp(aO[r]);
                ((float2*)(g_v + (row0 + r)*DD))[lane] =
                    make_float2(e0.x + e0.y + bvv.x, e1.x + e1.y + bvv.y);
            }

            // ---- DFT pass: bin = lane, packed twiddles ----
            {
                u64 re2[4] = {0,0,0,0}, im2[4] = {0,0,0,0};
                const ulonglong2* Twp = (const ulonglong2*)g_twp;
                #pragma unroll 4
                for (int d4 = 0; d4 < 16; d4++) {
                    ulonglong2 t0 = Twp[(2*d4)*32 + lane];
                    ulonglong2 t1 = Twp[(2*d4+1)*32 + lane];
                    #pragma unroll
                    for (int r = 0; r < 4; r++) {
                        ulonglong2 hh = ((const ulonglong2*)sh[warp][r])[d4];
                        re2[r] = fma2(hh.x, t0.x, re2[r]);
                        im2[r] = fma2(hh.x, t0.y, im2[r]);
                        re2[r] = fma2(hh.y, t1.x, re2[r]);
                        im2[r] = fma2(hh.y, t1.y, im2[r]);
                    }
                }
                #pragma unroll
                for (int r = 0; r < 4; r++) {
                    float2 rr = unp(re2[r]), ii = unp(im2[r]);
                    float re = rr.x + rr.y, im = ii.x + ii.y;
                    smag[warp][r][lane] = sqrtf(re*re + im*im);
                }
            }
            __syncwarp();

            // ---- gate: 8 lanes per row ----
            {
                int r   = lane >> 3;
                int bnd = lane & 7;
                const float* mg = smag[warp][r];
                float en = 0.25f * (mg[4*bnd] + mg[4*bnd+1] + mg[4*bnd+2] + mg[4*bnd+3]);
                float esum = en;
                esum += __shfl_xor_sync(0xffffffffu, esum, 1);
                esum += __shfl_xor_sync(0xffffffffu, esum, 2);
                esum += __shfl_xor_sync(0xffffffffu, esum, 4);
                float eni = en / fmaxf(esum, 1e-8f);
                float z0 = b1[2*bnd], z1 = b1[2*bnd+1];
                int gbase = lane & 24;
                #pragma unroll
                for (int i = 0; i < 8; i++) {
                    float ei = __shfl_sync(0xffffffffu, eni, gbase + i);
                    z0 = fmaf(ei, W1[i*16 + 2*bnd],     z0);
                    z1 = fmaf(ei, W1[i*16 + 2*bnd + 1], z1);
                }
                float s0 = z0 / (1.0f + expf(-z0)) * W2[2*bnd];
                float s1 = z1 / (1.0f + expf(-z1)) * W2[2*bnd+1];
                float hid = s0 + s1;
                hid += __shfl_xor_sync(0xffffffffu, hid, 1);
                hid += __shfl_xor_sync(0xffffffffu, hid, 2);
                hid += __shfl_xor_sync(0xffffffffu, hid, 4);
                if (bnd == 0) {
                    float z2 = hid + b2[0];
                    g_gam[row0 + r] = 0.5f + 0.49f / (1.0f + expf(-z2));
                }
            }
            __syncwarp();
        }
    }
    __syncthreads();   // pre writes visible to all warps (same CTA, same L1)

    // ================= SCAN phase: 4 threads per state row =================
    {
        const int d   = threadIdx.x >> 2;
        const int sub = threadIdx.x & 3;

        const ulonglong2* __restrict__ kp = (const ulonglong2*)(g_k + b*NN*DD + sub*16);
        const ulonglong2* __restrict__ qp = (const ulonglong2*)(g_q + b*NN*DD + sub*16);
        const float*  __restrict__ vp = g_v + b*NN*DD + d;
        const float*  __restrict__ gp = g_gam + b*NN;
        float*        __restrict__ op = g_o + b*NN*DD + d;

        u64 S2[8];
        #pragma unroll
        for (int i = 0; i < 8; i++) S2[i] = 0ull;

        #pragma unroll 1
        for (int t = 0; t < NN; t++) {
            ulonglong2 kA = kp[0], kB = kp[1], kC = kp[2], kD = kp[3];
            ulonglong2 qA = qp[0], qB = qp[1], qC = qp[2], qD = qp[3];
            kp += 16; qp += 16;
            float gc = *gp++;
            float vc = *vp; vp += DD;

            u64 k2[8] = {kA.x, kA.y, kB.x, kB.y, kC.x, kC.y, kD.x, kD.y};
            u64 q2[8] = {qA.x, qA.y, qB.x, qB.y, qC.x, qC.y, qD.x, qD.y};

            u64 pa = mul2(S2[0], k2[0]);
            pa = fma2(S2[1], k2[1], pa);
            pa = fma2(S2[2], k2[2], pa);
            pa = fma2(S2[3], k2[3], pa);
            u64 pb = mul2(S2[4], k2[4]);
            pb = fma2(S2[5], k2[5], pb);
            pb = fma2(S2[6], k2[6], pb);
            pb = fma2(S2[7], k2[7], pb);
            float2 ua = unp(pa), ub = unp(pb);
            float pred = (ua.x + ua.y) + (ub.x + ub.y);
            pred += __shfl_xor_sync(0xffffffffu, pred, 1);
            pred += __shfl_xor_sync(0xffffffffu, pred, 2);

            float delta = fminf(fmaxf(vc - pred, -5.0f), 5.0f);
            u64 g2 = dup2(gc), dl2 = dup2(delta);

            u64 oa, ob;
            S2[0] = upd2(S2[0], k2[0], g2, dl2);  oa = mul2(S2[0], q2[0]);
            S2[1] = upd2(S2[1], k2[1], g2, dl2);  oa = fma2(S2[1], q2[1], oa);
            S2[2] = upd2(S2[2], k2[2], g2, dl2);  oa = fma2(S2[2], q2[2], oa);
            S2[3] = upd2(S2[3], k2[3], g2, dl2);  oa = fma2(S2[3], q2[3], oa);
            S2[4] = upd2(S2[4], k2[4], g2, dl2);  ob = mul2(S2[4], q2[4]);
            S2[5] = upd2(S2[5], k2[5], g2, dl2);  ob = fma2(S2[5], q2[5], ob);
            S2[6] = upd2(S2[6], k2[6], g2, dl2);  ob = fma2(S2[6], q2[6], ob);
            S2[7] = upd2(S2[7], k2[7], g2, dl2);  ob = fma2(S2[7], q2[7], ob);

            float2 oa2 = unp(oa), ob2 = unp(ob);
            float o = (oa2.x + oa2.y) + (ob2.x + ob2.y);
            o += __shfl_xor_sync(0xffffffffu, o, 1);
            o += __shfl_xor_sync(0xffffffffu, o, 2);
            if (sub == 0) op[t*DD] = o;
        }
    }
    __syncthreads();   // scan outputs visible

    // ================= POST phase: 4 rows per warp per iteration =================
    {
        float2 gp2 = ((const float2*)g_post)[lane];
        float2 bov = ((const float2*)bo)[lane];
        for (int rb = warp*4; rb < NN; rb += 32) {
            const int row0 = b*NN + rb;
            #pragma unroll
            for (int r = 0; r < 4; r++) {
                float2 ov = ((const float2*)(g_o + (row0 + r)*DD))[lane];
                float s = ov.x + ov.y;
                #pragma unroll
                for (int o = 16; o; o >>= 1) s += __shfl_xor_sync(0xffffffffu, s, o);
                float mean = s * (1.0f/64.0f);
                float a0 = ov.x - mean, a1 = ov.y - mean;
                float ss = a0*a0 + a1*a1;
                #pragma unroll
                for (int o = 16; o; o >>= 1) ss += __shfl_xor_sync(0xffffffffu, ss, o);
                float rn = rsqrtf(ss * (1.0f/64.0f) + 1e-8f);
                sh[warp][r][2*lane]   = a0 * rn * gp2.x;
                sh[warp][r][2*lane+1] = a1 * rn * gp2.y;
            }
            __syncwarp();

            u64 aE[4], aO[4];
            MATVEC_PASS4(((const ulonglong2*)g_Wop), aE, aO)

            #pragma unroll
            for (int r = 0; r < 4; r++) {
                float2 e0 = unp(aE[r]), e1 = unp(aO[r]);
                int row = row0 + r;
                float2 xv = ((const float2*)(x + row*DD))[lane];
                ((float2*)(out + row*DD))[lane] =
                    make_float2(xv.x + e0.x + e0.y + bov.x,
                                xv.y + e1.x + e1.y + bov.y);
            }
            __syncwarp();
        }
    }
}

// ---------------- launch ----------------
extern "C" void kernel_launch(void* const* d_in, const int* in_sizes, int n_in,
                              void* d_out, int out_size)
{
    const float* x      = (const float*)d_in[0];
    const float* g_norm = (const float*)d_in[1];
    const float* Wq     = (const float*)d_in[2];
    const float* Wk     = (const float*)d_in[3];
    const float* Wv     = (const float*)d_in[4];
    const float* bv     = (const float*)d_in[5];
    const float* Wo     = (const float*)d_in[6];
    const float* bo     = (const float*)d_in[7];
    const float* g_post = (const float*)d_in[8];
    const float* W1     = (const float*)d_in[9];
    const float* b1     = (const float*)d_in[10];
    const float* W2     = (const float*)d_in[11];
    const float* b2     = (const float*)d_in[12];
    float* out          = (float*)d_out;

    init_kernel<<<20, 256>>>(Wq, Wk, Wv, Wo);
    fused_kernel<<<BB, 256>>>(x, g_norm, bv, W1, b1, W2, b2, g_post, bo, out);
}